// round 4
// baseline (speedup 1.0000x reference)
#include <cuda_runtime.h>
#include <cstdint>

#define NL 1024
#define NB 32
#define NT 12
#define NF 4
#define NH 64

// Scratch (static device globals: allocation-free rule)
__device__ float g_h[2][NL * NH * NB];      // hidden, layout [L][H][B], double buffered
__device__ float g_xT[NT * NL * NF * NB];   // x transposed to [T][L][F][B]
__device__ float g_bias[4][NL * NH];        // [0]=b_rh+b_ri, [1]=b_uh+b_ui, [2]=b_nh, [3]=b_ni ; layout [L][H]

// packed f32x2 FMA: d = a*b + c (two independent fp32 lanes, full-rate on sm_10x)
__device__ __forceinline__ float2 ffma2(float2 a, float2 b, float2 c) {
    unsigned long long ua = *reinterpret_cast<unsigned long long*>(&a);
    unsigned long long ub = *reinterpret_cast<unsigned long long*>(&b);
    unsigned long long uc = *reinterpret_cast<unsigned long long*>(&c);
    unsigned long long ud;
    asm("fma.rn.f32x2 %0, %1, %2, %3;" : "=l"(ud) : "l"(ua), "l"(ub), "l"(uc));
    return *reinterpret_cast<float2*>(&ud);
}

__device__ __forceinline__ void cp16(uint32_t dst, const void* src) {
    asm volatile("cp.async.cg.shared.global [%0], [%1], 16;\n" :: "r"(dst), "l"(src));
}
__device__ __forceinline__ void cp_commit() {
    asm volatile("cp.async.commit_group;\n" ::: "memory");
}
template <int N>
__device__ __forceinline__ void cp_wait() {
    asm volatile("cp.async.wait_group %0;\n" :: "n"(N) : "memory");
}

__device__ __forceinline__ float fsigmoid(float x) {
    return __fdividef(1.0f, 1.0f + __expf(-x));
}
__device__ __forceinline__ float ftanh_fast(float x) {
    float e = __expf(2.0f * x);                 // inf for large x -> n = 1 (correct)
    return 1.0f - __fdividef(2.0f, e + 1.0f);   // e->0 -> -1 (correct)
}

// ---------------- prep kernels ----------------

__global__ void prep_bias(const float* __restrict__ b_rh, const float* __restrict__ b_ri,
                          const float* __restrict__ b_uh, const float* __restrict__ b_ui,
                          const float* __restrict__ b_nh, const float* __restrict__ b_ni) {
    int idx = blockIdx.x * blockDim.x + threadIdx.x;   // 4 * L * H = 262144
    if (idx >= 4 * NL * NH) return;
    int q = idx >> 16;           // which bias set
    int r = idx & 65535;         // l*64 + k
    int l = r >> 6;
    int k = r & 63;
    int src = k * NL + l;        // biases are [H][L]
    float v;
    if (q == 0)      v = b_rh[src] + b_ri[src];
    else if (q == 1) v = b_uh[src] + b_ui[src];
    else if (q == 2) v = b_nh[src];
    else             v = b_ni[src];
    g_bias[q][r] = v;
}

__global__ void prep_x(const float* __restrict__ x) {
    int idx = blockIdx.x * blockDim.x + threadIdx.x;   // T*L*F*B = 1572864
    if (idx >= NT * NL * NF * NB) return;
    int b = idx & 31;
    int f = (idx >> 5) & 3;
    int l = (idx >> 7) & 1023;
    int t = idx >> 17;
    g_xT[idx] = x[((b * NT + t) * NF + f) * NL + l];
}

// ---------------- GRU step kernel ----------------
// block = link l, 128 threads, 5 CTAs/SM. Thread tile: 4b x 4k x 3 gates (48 acc).
// Weights streamed as 4 chunks of 16 h-rows x 3 gates (12KB each) through a
// 2-buffer cp.async ring, so GEMM starts after the first 12KB and subsequent
// chunks stream under compute. x-GEMM + b_ni moved to the epilogue to keep the
// GEMM-phase register live set under the 102-reg / 5-CTA budget.
// smem: [0..3072) buf0, [3072..6144) buf1 (each [3][16][64]); [6144..8192) hatt [h][b].

template <bool FIRST>
__global__ void __launch_bounds__(128, 5)
step_kernel(const float* __restrict__ att,
            const float* __restrict__ w_rh, const float* __restrict__ w_uh, const float* __restrict__ w_nh,
            const float* __restrict__ w_ri, const float* __restrict__ w_ui, const float* __restrict__ w_ni,
            int t, int cur, int nxt) {
    extern __shared__ float smem[];
    float* sHatt = smem + 6144;

    const int l   = blockIdx.x;
    const int tid = threadIdx.x;
    const int k0 = (tid & 15) * 4;
    const int b0 = (tid >> 4) * 4;

    const float* wh0 = w_rh + l * 4096;
    const float* wh1 = w_uh + l * 4096;
    const float* wh2 = w_nh + l * 4096;

    auto issue_chunk = [&](int c, int bufIdx) {
        uint32_t dstb = (uint32_t)__cvta_generic_to_shared(smem) + (uint32_t)(bufIdx * 3072) * 4u;
        const float4* s0 = (const float4*)(wh0 + c * 1024);
        const float4* s1 = (const float4*)(wh1 + c * 1024);
        const float4* s2 = (const float4*)(wh2 + c * 1024);
        cp16(dstb + tid * 16,                  s0 + tid);
        cp16(dstb + (tid + 128) * 16,          s0 + tid + 128);
        cp16(dstb + 4096  + tid * 16,          s1 + tid);
        cp16(dstb + 4096  + (tid + 128) * 16,  s1 + tid + 128);
        cp16(dstb + 8192  + tid * 16,          s2 + tid);
        cp16(dstb + 8192  + (tid + 128) * 16,  s2 + tid + 128);
        cp_commit();
    };

    if (!FIRST) {
        // prefetch first two weight chunks, then build hatt under their latency
        issue_chunk(0, 0);
        issue_chunk(1, 1);

        // graph attention: banded mix of neighbor hidden states
        float a0 = att[l * NL + l];
        float am = (l > 0)      ? att[l * NL + l - 1] : 0.0f;
        float ap = (l < NL - 1) ? att[l * NL + l + 1] : 0.0f;
        const int lm = (l > 0) ? l - 1 : l;
        const int lp = (l < NL - 1) ? l + 1 : l;
        const float4* hm = (const float4*)(g_h[cur] + lm * (NH * NB));
        const float4* hc = (const float4*)(g_h[cur] + l  * (NH * NB));
        const float4* hp = (const float4*)(g_h[cur] + lp * (NH * NB));
        float4* sh = (float4*)sHatt;
#pragma unroll
        for (int i = 0; i < 4; i++) {
            int j = tid + i * 128;
            float4 m = hm[j], c4 = hc[j], p = hp[j];
            float4 v;
            v.x = am * m.x + a0 * c4.x + ap * p.x;
            v.y = am * m.y + a0 * c4.y + ap * p.y;
            v.z = am * m.z + a0 * c4.z + ap * p.z;
            v.w = am * m.w + a0 * c4.w + ap * p.w;
            sh[j] = v;
        }
    }

    // --- accumulators: init from combined biases (x-part added in epilogue) ---
    float2 aR2[8], aZ2[8], aN2[8];
    float* accR  = (float*)aR2;
    float* accZ  = (float*)aZ2;
    float* accNH = (float*)aN2;
    {
        float4 br = *(const float4*)&g_bias[0][l * 64 + k0];
        float4 bz = *(const float4*)&g_bias[1][l * 64 + k0];
        float4 bh = *(const float4*)&g_bias[2][l * 64 + k0];
#pragma unroll
        for (int bb = 0; bb < 4; bb++) {
            aR2[bb * 2 + 0] = make_float2(br.x, br.y);  aR2[bb * 2 + 1] = make_float2(br.z, br.w);
            aZ2[bb * 2 + 0] = make_float2(bz.x, bz.y);  aZ2[bb * 2 + 1] = make_float2(bz.z, bz.w);
            aN2[bb * 2 + 0] = make_float2(bh.x, bh.y);  aN2[bb * 2 + 1] = make_float2(bh.z, bh.w);
        }
    }

    if (!FIRST) {
        auto gemm_chunk = [&](int bufIdx, int hbase) {
            const float* buf = smem + bufIdx * 3072;
#pragma unroll
            for (int hh = 0; hh < 16; hh++) {
                float4 hv = *(const float4*)&sHatt[(hbase + hh) * 32 + b0];
                float2 hb[4] = { {hv.x, hv.x}, {hv.y, hv.y}, {hv.z, hv.z}, {hv.w, hv.w} };
                float4 wr = *(const float4*)&buf[hh * 64 + k0];
                float4 wu = *(const float4*)&buf[1024 + hh * 64 + k0];
                float4 wn = *(const float4*)&buf[2048 + hh * 64 + k0];
                float2 wr0 = make_float2(wr.x, wr.y), wr1 = make_float2(wr.z, wr.w);
                float2 wu0 = make_float2(wu.x, wu.y), wu1 = make_float2(wu.z, wu.w);
                float2 wn0 = make_float2(wn.x, wn.y), wn1 = make_float2(wn.z, wn.w);
#pragma unroll
                for (int bb = 0; bb < 4; bb++) {
                    aR2[bb * 2 + 0] = ffma2(hb[bb], wr0, aR2[bb * 2 + 0]);
                    aR2[bb * 2 + 1] = ffma2(hb[bb], wr1, aR2[bb * 2 + 1]);
                    aZ2[bb * 2 + 0] = ffma2(hb[bb], wu0, aZ2[bb * 2 + 0]);
                    aZ2[bb * 2 + 1] = ffma2(hb[bb], wu1, aZ2[bb * 2 + 1]);
                    aN2[bb * 2 + 0] = ffma2(hb[bb], wn0, aN2[bb * 2 + 0]);
                    aN2[bb * 2 + 1] = ffma2(hb[bb], wn1, aN2[bb * 2 + 1]);
                }
            }
        };

        cp_wait<1>(); __syncthreads();            // chunk 0 + hatt ready
        gemm_chunk(0, 0);
        __syncthreads();                          // buf0 free
        issue_chunk(2, 0);
        cp_wait<1>(); __syncthreads();            // chunk 1 ready
        gemm_chunk(1, 16);
        __syncthreads();                          // buf1 free
        issue_chunk(3, 1);
        cp_wait<1>(); __syncthreads();            // chunk 2 ready
        gemm_chunk(0, 32);
        cp_wait<0>(); __syncthreads();            // chunk 3 ready
        gemm_chunk(1, 48);
    }

    // --- epilogue: x-GEMM (F=4) + b_ni, then gates + write h_next ---
    float2 xiN2[8];
    float* xiN = (float*)xiN2;
    {
        float4 bn = *(const float4*)&g_bias[3][l * 64 + k0];
#pragma unroll
        for (int bb = 0; bb < 4; bb++) {
            xiN2[bb * 2 + 0] = make_float2(bn.x, bn.y);
            xiN2[bb * 2 + 1] = make_float2(bn.z, bn.w);
        }
        const float* xb = g_xT + (t * NL + l) * (NF * NB);
#pragma unroll
        for (int f = 0; f < 4; f++) {
            float4 xv = *(const float4*)&xb[f * 32 + b0];
            float2 xs[4] = { {xv.x, xv.x}, {xv.y, xv.y}, {xv.z, xv.z}, {xv.w, xv.w} };
            float4 wr = *(const float4*)&w_ri[l * 256 + f * 64 + k0];
            float4 wu = *(const float4*)&w_ui[l * 256 + f * 64 + k0];
            float4 wn = *(const float4*)&w_ni[l * 256 + f * 64 + k0];
            float2 wr0 = make_float2(wr.x, wr.y), wr1 = make_float2(wr.z, wr.w);
            float2 wu0 = make_float2(wu.x, wu.y), wu1 = make_float2(wu.z, wu.w);
            float2 wn0 = make_float2(wn.x, wn.y), wn1 = make_float2(wn.z, wn.w);
#pragma unroll
            for (int bb = 0; bb < 4; bb++) {
                aR2[bb * 2 + 0] = ffma2(xs[bb], wr0, aR2[bb * 2 + 0]);
                aR2[bb * 2 + 1] = ffma2(xs[bb], wr1, aR2[bb * 2 + 1]);
                aZ2[bb * 2 + 0] = ffma2(xs[bb], wu0, aZ2[bb * 2 + 0]);
                aZ2[bb * 2 + 1] = ffma2(xs[bb], wu1, aZ2[bb * 2 + 1]);
                xiN2[bb * 2 + 0] = ffma2(xs[bb], wn0, xiN2[bb * 2 + 0]);
                xiN2[bb * 2 + 1] = ffma2(xs[bb], wn1, xiN2[bb * 2 + 1]);
            }
        }
    }

    const float* hcur = g_h[cur] + l * (NH * NB);
    float* hnxt = g_h[nxt] + l * (NH * NB);
#pragma unroll
    for (int kk = 0; kk < 4; kk++) {
        int k = k0 + kk;
        float holdv[4] = {0.f, 0.f, 0.f, 0.f};
        if (!FIRST) {
            float4 h4 = *(const float4*)&hcur[k * 32 + b0];
            holdv[0] = h4.x; holdv[1] = h4.y; holdv[2] = h4.z; holdv[3] = h4.w;
        }
        float o[4];
#pragma unroll
        for (int bb = 0; bb < 4; bb++) {
            int p = bb * 4 + kk;
            float r = fsigmoid(accR[p]);
            float z = fsigmoid(accZ[p]);
            float n = ftanh_fast(xiN[p] + r * accNH[p]);
            o[bb] = n + z * (holdv[bb] - n);
        }
        *(float4*)&hnxt[k * 32 + b0] = make_float4(o[0], o[1], o[2], o[3]);
    }
}

// ---------------- output head ----------------
__global__ void fc_kernel(const float* __restrict__ w_fc, const float* __restrict__ b_fc,
                          float* __restrict__ out) {
    int l = blockIdx.x;
    int b = threadIdx.x;   // 32 threads
    const float* h = g_h[0] + l * (NH * NB);
    float acc = b_fc[l];
#pragma unroll 8
    for (int k = 0; k < NH; k++) acc += h[k * 32 + b] * w_fc[l * NH + k];
    out[b * NL + l] = acc;   // [B][O=1][L]
}

// ---------------- launch ----------------
#define STEP_SMEM (8192 * 4)   // 32 KB: 2x12KB weight ring + 8KB hatt (<=48KB default limit)

extern "C" void kernel_launch(void* const* d_in, const int* in_sizes, int n_in,
                              void* d_out, int out_size) {
    const float* x    = (const float*)d_in[0];
    const float* att  = (const float*)d_in[1];
    const float* w_rh = (const float*)d_in[2];
    const float* b_rh = (const float*)d_in[3];
    const float* w_ri = (const float*)d_in[4];
    const float* b_ri = (const float*)d_in[5];
    const float* w_uh = (const float*)d_in[6];
    const float* b_uh = (const float*)d_in[7];
    const float* w_ui = (const float*)d_in[8];
    const float* b_ui = (const float*)d_in[9];
    const float* w_nh = (const float*)d_in[10];
    const float* b_nh = (const float*)d_in[11];
    const float* w_ni = (const float*)d_in[12];
    const float* b_ni = (const float*)d_in[13];
    const float* w_fc = (const float*)d_in[14];
    const float* b_fc = (const float*)d_in[15];

    prep_bias<<<1024, 256>>>(b_rh, b_ri, b_uh, b_ui, b_nh, b_ni);
    prep_x<<<6144, 256>>>(x);

    // t=0: h=0, skip attention + hidden GEMM
    step_kernel<true><<<1024, 128, STEP_SMEM>>>(att, w_rh, w_uh, w_nh, w_ri, w_ui, w_ni, 0, 0, 1);
    for (int t = 1; t < NT; t++) {
        step_kernel<false><<<1024, 128, STEP_SMEM>>>(att, w_rh, w_uh, w_nh, w_ri, w_ui, w_ni,
                                                     t, t & 1, (t + 1) & 1);
    }
    // after t=11 (writes buffer 0)
    fc_kernel<<<1024, 32>>>(w_fc, b_fc, (float*)d_out);
}